// round 3
// baseline (speedup 1.0000x reference)
#include <cuda_runtime.h>
#include <cuda_bf16.h>
#include <math.h>
#include <stdint.h>

#define Bn 1024
#define Pn 8
#define Dn 2048
#define PDn (Pn * Dn)      // 16384
#define NUM_IDS 64
#define MARGIN 0.3f
#define EPSV 1e-12f

// ---------------- device scratch (static; no allocations) ----------------
__device__ int   g_lab[Bn];
__device__ int   g_idx[NUM_IDS * Bn];
__device__ int   g_cnt[NUM_IDS];
__device__ float g_centers[NUM_IDS * PDn];         // 4 MB
__device__ float g_sq[Bn * Pn];
__device__ float g_dpp[Bn * Pn];
__device__ float g_dap[Bn];
__device__ float g_dpair[(size_t)Pn * Bn * Bn];    // 32 MB
__device__ float g_part[256 * 2];
__device__ __nv_bfloat16 g_fb16[(size_t)Bn * PDn]; // 32 MB bf16 copy of f

// ======================= PTX helpers (arch-agnostic) =======================
__device__ __forceinline__ uint32_t smem_u32(const void* p) {
    uint32_t a;
    asm("{ .reg .u64 t; cvta.to.shared.u64 t, %1; cvt.u32.u64 %0, t; }"
        : "=r"(a) : "l"(p));
    return a;
}

__device__ __forceinline__ void cp_async16(uint32_t saddr, const void* gaddr) {
    asm volatile("cp.async.cg.shared.global [%0], [%1], 16;"
                 :: "r"(saddr), "l"(gaddr) : "memory");
}
__device__ __forceinline__ void cp_commit() {
    asm volatile("cp.async.commit_group;" ::: "memory");
}
__device__ __forceinline__ void cp_wait1() {
    asm volatile("cp.async.wait_group 1;" ::: "memory");
}

__device__ __forceinline__ void ldsm4(uint32_t r[4], uint32_t addr) {
    asm volatile("ldmatrix.sync.aligned.m8n8.x4.shared.b16 {%0,%1,%2,%3}, [%4];"
                 : "=r"(r[0]), "=r"(r[1]), "=r"(r[2]), "=r"(r[3]) : "r"(addr));
}

__device__ __forceinline__ void mma_bf16(float c[4], const uint32_t a[4],
                                         const uint32_t b[2]) {
    asm volatile(
        "mma.sync.aligned.m16n8k16.row.col.f32.bf16.bf16.f32 "
        "{%0,%1,%2,%3}, {%4,%5,%6,%7}, {%8,%9}, {%0,%1,%2,%3};"
        : "+f"(c[0]), "+f"(c[1]), "+f"(c[2]), "+f"(c[3])
        : "r"(a[0]), "r"(a[1]), "r"(a[2]), "r"(a[3]), "r"(b[0]), "r"(b[1]));
}

// SW128 swizzle over 128-byte rows: seg' = seg ^ (row & 7)
__device__ __forceinline__ uint32_t swz(uint32_t base, int row, int seg) {
    return base + (((uint32_t)(row * 128 + seg * 16)) ^ (uint32_t)((row & 7) << 4));
}

// ---------------- K-1: fp32 -> bf16 convert -------------------------------
__global__ void conv_kernel(const float* __restrict__ f) {
    size_t i = ((size_t)blockIdx.x * 256 + threadIdx.x) * 8;
    float4 a = *(const float4*)(f + i);
    float4 b = *(const float4*)(f + i + 4);
    __nv_bfloat162 o0 = __floats2bfloat162_rn(a.x, a.y);
    __nv_bfloat162 o1 = __floats2bfloat162_rn(a.z, a.w);
    __nv_bfloat162 o2 = __floats2bfloat162_rn(b.x, b.y);
    __nv_bfloat162 o3 = __floats2bfloat162_rn(b.z, b.w);
    uint4 o;
    o.x = *(uint32_t*)&o0; o.y = *(uint32_t*)&o1;
    o.z = *(uint32_t*)&o2; o.w = *(uint32_t*)&o3;
    *(uint4*)(g_fb16 + i) = o;
}

// ---------------- K0: labels + per-id lists --------------------------------
__global__ void build_kernel(const int* __restrict__ raw) {
    __shared__ int is64;
    int t = threadIdx.x;
    if (t == 0) is64 = 1;
    __syncthreads();
    for (int k = t; k < 512; k += 256)
        if (raw[2 * k + 1] != 0) is64 = 0;
    __syncthreads();
    int w64 = is64;
    for (int b = t; b < Bn; b += 256) g_lab[b] = w64 ? raw[2 * b] : raw[b];
    __syncthreads();
    if (t < NUM_IDS) {
        int c = 0;
        for (int b = 0; b < Bn; b++)
            if (g_lab[b] == t) g_idx[t * Bn + (c++)] = b;
        g_cnt[t] = c;
    }
}

// ---------------- K1: class centers ---------------------------------------
__global__ void centers_kernel(const float* __restrict__ f) {
    int id  = blockIdx.y;
    int dim = blockIdx.x * 256 + threadIdx.x;
    int cnt = g_cnt[id];
    float acc = 0.f;
    const int* lst = g_idx + id * Bn;
    for (int s = 0; s < cnt; s++) acc += f[(size_t)lst[s] * PDn + dim];
    g_centers[(size_t)id * PDn + dim] = acc / fmaxf((float)cnt, 1.0f);
}

// ---------------- K2: per-(i,p) dist-to-center + squared norm -------------
__global__ void dap_kernel(const float* __restrict__ f) {
    int i = blockIdx.x, p = blockIdx.y, tid = threadIdx.x;
    const float* fr = f + (size_t)i * PDn + (size_t)p * Dn;
    const float* cr = g_centers + (size_t)g_lab[i] * PDn + (size_t)p * Dn;
    float d = 0.f, s = 0.f;
    for (int k = tid; k < Dn; k += 256) {
        float v = fr[k], e = v - cr[k];
        d += e * e; s += v * v;
    }
    __shared__ float sd[256], ss[256];
    sd[tid] = d; ss[tid] = s;
    __syncthreads();
    for (int o = 128; o > 0; o >>= 1) {
        if (tid < o) { sd[tid] += sd[tid + o]; ss[tid] += ss[tid + o]; }
        __syncthreads();
    }
    if (tid == 0) {
        g_dpp[i * Pn + p] = sqrtf(fmaxf(sd[0], EPSV));
        g_sq[i * Pn + p]  = ss[0];
    }
}

__global__ void dapsum_kernel() {
    int i = blockIdx.x * 256 + threadIdx.x;
    if (i < Bn) {
        float s = 0.f;
        #pragma unroll
        for (int p = 0; p < Pn; p++) s += g_dpp[i * Pn + p];
        g_dap[i] = s;
    }
}

// ---------------- K3: bf16 mma.sync GEMM + sqrt epilogue -------------------
// CTA: (tj, ti, p). M=N=128, K=2048 in 32 chunks of 64. 3-stage cp.async.
#define STAGES 3
#define CHUNKS 32
#define STAGE_BYTES 32768               // A 16KB + B 16KB
#define SMEM_DYN (STAGES * STAGE_BYTES + 1024)

__device__ __forceinline__ void load_chunk(const __nv_bfloat16* __restrict__ Ab,
                                           const __nv_bfloat16* __restrict__ Bb,
                                           uint32_t stBase, int kt) {
    int t = threadIdx.x;   // 256 threads; 2048 16B segments per chunk
    #pragma unroll
    for (int u = 0; u < 8; u++) {
        int id   = t + (u << 8);              // 0..2047
        int half = id >> 10;                  // 0 = A, 1 = B
        int rid  = id & 1023;
        int row  = rid >> 3;
        int seg  = rid & 7;
        const __nv_bfloat16* g =
            (half ? Bb : Ab) + (size_t)row * PDn + kt * 64 + seg * 8;
        uint32_t s = swz(stBase + (half ? 16384u : 0u), row, seg);
        cp_async16(s, g);
    }
    cp_commit();
}

__global__ void __launch_bounds__(256, 1)
gemm_mma_kernel(const __nv_bfloat16* __restrict__ fb) {
    extern __shared__ char dsm[];
    __shared__ float sqi[128], sqj[128];

    uint32_t sb = (smem_u32(dsm) + 1023u) & ~1023u;
    int tid = threadIdx.x, wid = tid >> 5, lid = tid & 31;
    int p = blockIdx.z, ti = blockIdx.y * 128, tj = blockIdx.x * 128;

    int wm = (wid & 3) * 32;    // warp M offset (4 warps)
    int wn = (wid >> 2) * 64;   // warp N offset (2 warps)

    if (tid < 128) {
        sqi[tid] = g_sq[(ti + tid) * Pn + p];
        sqj[tid] = g_sq[(tj + tid) * Pn + p];
    }

    const __nv_bfloat16* Ab = fb + (size_t)ti * PDn + (size_t)p * Dn;
    const __nv_bfloat16* Bb = fb + (size_t)tj * PDn + (size_t)p * Dn;

    // preload stages 0,1
    load_chunk(Ab, Bb, sb + 0 * STAGE_BYTES, 0);
    load_chunk(Ab, Bb, sb + 1 * STAGE_BYTES, 1);

    float acc[2][8][4];
    #pragma unroll
    for (int mt = 0; mt < 2; mt++)
        #pragma unroll
        for (int nt = 0; nt < 8; nt++)
            #pragma unroll
            for (int c = 0; c < 4; c++) acc[mt][nt][c] = 0.f;

    int q = lid >> 3, r8 = lid & 7;

    for (int kt = 0; kt < CHUNKS; kt++) {
        uint32_t aBase = sb + (kt % STAGES) * STAGE_BYTES;
        uint32_t bBase = aBase + 16384;

        cp_wait1();
        __syncthreads();

        if (kt + 2 < CHUNKS)
            load_chunk(Ab, Bb, sb + ((kt + 2) % STAGES) * STAGE_BYTES, kt + 2);
        else
            cp_commit();   // keep group numbering consistent

        #pragma unroll
        for (int ks = 0; ks < 4; ks++) {
            uint32_t a[2][4];
            #pragma unroll
            for (int mt = 0; mt < 2; mt++) {
                int row = wm + mt * 16 + (q & 1) * 8 + r8;
                int seg = ks * 2 + (q >> 1);
                ldsm4(a[mt], swz(aBase, row, seg));
            }
            uint32_t b[8][2];
            #pragma unroll
            for (int pt = 0; pt < 4; pt++) {
                int nrow = wn + pt * 16 + (q >> 1) * 8 + r8;
                int seg  = ks * 2 + (q & 1);
                uint32_t r[4];
                ldsm4(r, swz(bBase, nrow, seg));
                b[2 * pt][0] = r[0]; b[2 * pt][1] = r[1];
                b[2 * pt + 1][0] = r[2]; b[2 * pt + 1][1] = r[3];
            }
            #pragma unroll
            for (int mt = 0; mt < 2; mt++)
                #pragma unroll
                for (int nt = 0; nt < 8; nt++)
                    mma_bf16(acc[mt][nt], a[mt], b[nt]);
        }
        __syncthreads();
    }

    // epilogue: dpair = sqrt(max(sq_i + sq_j - 2*inner, eps))
    int rlo = lid >> 2;           // 0..7
    int cq  = (lid & 3) * 2;      // 0,2,4,6
    #pragma unroll
    for (int mt = 0; mt < 2; mt++) {
        int r0l = wm + mt * 16 + rlo;
        int r1l = r0l + 8;
        float sq0 = sqi[r0l], sq1 = sqi[r1l];
        size_t b0 = ((size_t)p << 20) + ((size_t)(ti + r0l) << 10) + tj;
        size_t b1 = ((size_t)p << 20) + ((size_t)(ti + r1l) << 10) + tj;
        #pragma unroll
        for (int nt = 0; nt < 8; nt++) {
            int cl = wn + nt * 8 + cq;
            float sc0 = sqj[cl], sc1 = sqj[cl + 1];
            float* c = acc[mt][nt];
            float2 v0, v1;
            v0.x = sqrtf(fmaxf(sq0 + sc0 - 2.0f * c[0], EPSV));
            v0.y = sqrtf(fmaxf(sq0 + sc1 - 2.0f * c[1], EPSV));
            v1.x = sqrtf(fmaxf(sq1 + sc0 - 2.0f * c[2], EPSV));
            v1.y = sqrtf(fmaxf(sq1 + sc1 - 2.0f * c[3], EPSV));
            *(float2*)&g_dpair[b0 + cl] = v0;
            *(float2*)&g_dpair[b1 + cl] = v1;
        }
    }
}

// ---------------- K4: masked margin reduction ------------------------------
__global__ void epilogue_kernel() {
    int tid = threadIdx.x;
    float accv = 0.f, accm = 0.f;
    int base = blockIdx.x * 4096;
    for (int t = 0; t < 16; t++) {
        int idx = base + t * 256 + tid;
        int i = idx >> 10, j = idx & 1023;
        if (g_lab[i] != g_lab[j]) {
            float daa = 0.f;
            #pragma unroll
            for (int p = 0; p < Pn; p++)
                daa += g_dpair[((size_t)p << 20) + idx];
            float v = g_dap[i] + g_dap[j] - daa + MARGIN;
            accv += fmaxf(v, 0.f);
            accm += 1.f;
        }
    }
    __shared__ float sv[256], sm[256];
    sv[tid] = accv; sm[tid] = accm;
    __syncthreads();
    for (int o = 128; o > 0; o >>= 1) {
        if (tid < o) { sv[tid] += sv[tid + o]; sm[tid] += sm[tid + o]; }
        __syncthreads();
    }
    if (tid == 0) {
        g_part[blockIdx.x * 2 + 0] = sv[0];
        g_part[blockIdx.x * 2 + 1] = sm[0];
    }
}

__global__ void finalize_kernel(float* __restrict__ out) {
    int tid = threadIdx.x;
    __shared__ float sv[256], sm[256];
    sv[tid] = g_part[tid * 2 + 0];
    sm[tid] = g_part[tid * 2 + 1];
    __syncthreads();
    for (int o = 128; o > 0; o >>= 1) {
        if (tid < o) { sv[tid] += sv[tid + o]; sm[tid] += sm[tid + o]; }
        __syncthreads();
    }
    if (tid == 0) out[0] = sv[0] / sm[0];
}

// ---------------- launch ----------------------------------------------------
extern "C" void kernel_launch(void* const* d_in, const int* in_sizes, int n_in,
                              void* d_out, int out_size) {
    const float* f    = (const float*)d_in[0];
    const int*   labr = (const int*)d_in[1];
    float*       out  = (float*)d_out;

    cudaFuncSetAttribute(gemm_mma_kernel,
                         cudaFuncAttributeMaxDynamicSharedMemorySize, SMEM_DYN);

    conv_kernel<<<(Bn * PDn) / (256 * 8), 256>>>(f);
    build_kernel<<<1, 256>>>(labr);
    centers_kernel<<<dim3(PDn / 256, NUM_IDS), 256>>>(f);
    dap_kernel<<<dim3(Bn, Pn), 256>>>(f);
    dapsum_kernel<<<4, 256>>>();
    gemm_mma_kernel<<<dim3(8, 8, 8), 256, SMEM_DYN>>>(g_fb16);
    epilogue_kernel<<<256, 256>>>();
    finalize_kernel<<<1, 256>>>(out);
}

// round 4
// speedup vs baseline: 2.0634x; 2.0634x over previous
#include <cuda_runtime.h>
#include <cuda_bf16.h>
#include <math.h>
#include <stdint.h>

#define Bn 1024
#define Pn 8
#define Dn 2048
#define PDn (Pn * Dn)      // 16384
#define NUM_IDS 64
#define MARGIN 0.3f
#define EPSV 1e-12f

// ---------------- device scratch (static; no allocations) ----------------
__device__ int   g_lab[Bn];
__device__ int   g_idx[NUM_IDS * Bn];
__device__ int   g_cnt[NUM_IDS];
__device__ float g_centers[NUM_IDS * PDn];         // 4 MB
__device__ float g_sq[Bn * Pn];
__device__ float g_dpp[Bn * Pn];
__device__ float g_dap[Bn];
__device__ float g_dpair[(size_t)Pn * Bn * Bn];    // 32 MB
__device__ float g_part[256 * 2];

// ======================= f32x2 helpers =======================
__device__ __forceinline__ unsigned long long bcast2(float x) {
    unsigned long long r;
    asm("mov.b64 %0, {%1, %1};" : "=l"(r) : "f"(x));
    return r;
}
__device__ __forceinline__ void fma2(unsigned long long& d,
                                     unsigned long long a,
                                     unsigned long long b) {
    asm("fma.rn.f32x2 %0, %1, %2, %0;" : "+l"(d) : "l"(a), "l"(b));
}
__device__ __forceinline__ float2 unpack2(unsigned long long v) {
    float2 f;
    asm("mov.b64 {%0, %1}, %2;" : "=f"(f.x), "=f"(f.y) : "l"(v));
    return f;
}

// ---------------- K0: labels + per-id lists --------------------------------
__global__ void build_kernel(const int* __restrict__ raw) {
    __shared__ int is64;
    int t = threadIdx.x;
    if (t == 0) is64 = 1;
    __syncthreads();
    for (int k = t; k < 512; k += 256)
        if (raw[2 * k + 1] != 0) is64 = 0;
    __syncthreads();
    int w64 = is64;
    for (int b = t; b < Bn; b += 256) g_lab[b] = w64 ? raw[2 * b] : raw[b];
    __syncthreads();
    if (t < NUM_IDS) {
        int c = 0;
        for (int b = 0; b < Bn; b++)
            if (g_lab[b] == t) g_idx[t * Bn + (c++)] = b;
        g_cnt[t] = c;
    }
}

// ---------------- K1: class centers ---------------------------------------
__global__ void centers_kernel(const float* __restrict__ f) {
    int id  = blockIdx.y;
    int dim = blockIdx.x * 256 + threadIdx.x;
    int cnt = g_cnt[id];
    float acc = 0.f;
    const int* lst = g_idx + id * Bn;
    for (int s = 0; s < cnt; s++) acc += f[(size_t)lst[s] * PDn + dim];
    g_centers[(size_t)id * PDn + dim] = acc / fmaxf((float)cnt, 1.0f);
}

// ---------------- K2: per-(i,p) dist-to-center + squared norm -------------
__global__ void dap_kernel(const float* __restrict__ f) {
    int i = blockIdx.x, p = blockIdx.y, tid = threadIdx.x;
    const float* fr = f + (size_t)i * PDn + (size_t)p * Dn;
    const float* cr = g_centers + (size_t)g_lab[i] * PDn + (size_t)p * Dn;
    float d = 0.f, s = 0.f;
    for (int k = tid; k < Dn; k += 256) {
        float v = fr[k], e = v - cr[k];
        d += e * e; s += v * v;
    }
    __shared__ float sd[256], ss[256];
    sd[tid] = d; ss[tid] = s;
    __syncthreads();
    for (int o = 128; o > 0; o >>= 1) {
        if (tid < o) { sd[tid] += sd[tid + o]; ss[tid] += ss[tid + o]; }
        __syncthreads();
    }
    if (tid == 0) {
        g_dpp[i * Pn + p] = sqrtf(fmaxf(sd[0], EPSV));
        g_sq[i * Pn + p]  = ss[0];
    }
}

__global__ void dapsum_kernel() {
    int i = blockIdx.x * 256 + threadIdx.x;
    if (i < Bn) {
        float s = 0.f;
        #pragma unroll
        for (int p = 0; p < Pn; p++) s += g_dpp[i * Pn + p];
        g_dap[i] = s;
    }
}

// ---------------- K3: fp32 GEMM via packed fma.rn.f32x2 --------------------
// CTA: (tj, ti, p). Tile 128x128, 128 threads, thread tile 8i x 16j.
// Accumulators packed along j (2 floats per 64-bit reg).
#define KC 8           // k per chunk
#define NCHUNK (Dn / KC)   // 256
#define SSTRIDE 132

__global__ void __launch_bounds__(128)
gemm_f32x2_kernel(const float* __restrict__ f) {
    __shared__ float As[2][KC][SSTRIDE];
    __shared__ float Bs[2][KC][SSTRIDE];
    __shared__ float sqi[128], sqj[128];

    int tid = threadIdx.x;
    int p = blockIdx.z, ti = blockIdx.y * 128, tj = blockIdx.x * 128;
    int tx = tid & 7, ty = tid >> 3;     // 8 x 16 thread grid
    int tm = ty * 8, tn = tx * 16;

    sqi[tid] = g_sq[(ti + tid) * Pn + p];
    sqj[tid] = g_sq[(tj + tid) * Pn + p];

    const float* Ab = f + (size_t)ti * PDn + (size_t)p * Dn;
    const float* Bb = f + (size_t)tj * PDn + (size_t)p * Dn;

    // staging indices: per chunk 128 rows x 8 floats = 256 float4 per matrix,
    // 2 per thread: idx = tid + u*128; row = idx>>1; c4 = idx&1
    int r0 = tid >> 1, c0 = tid & 1;
    int r1 = (tid + 128) >> 1, c1 = tid & 1;   // (tid+128)&1 == tid&1

    // prologue: load + store chunk 0
    {
        float4 a0 = *(const float4*)(Ab + (size_t)r0 * PDn + c0 * 4);
        float4 a1 = *(const float4*)(Ab + (size_t)r1 * PDn + c1 * 4);
        float4 b0 = *(const float4*)(Bb + (size_t)r0 * PDn + c0 * 4);
        float4 b1 = *(const float4*)(Bb + (size_t)r1 * PDn + c1 * 4);
        int k0 = c0 * 4, k1 = c1 * 4;
        As[0][k0+0][r0]=a0.x; As[0][k0+1][r0]=a0.y; As[0][k0+2][r0]=a0.z; As[0][k0+3][r0]=a0.w;
        As[0][k1+0][r1]=a1.x; As[0][k1+1][r1]=a1.y; As[0][k1+2][r1]=a1.z; As[0][k1+3][r1]=a1.w;
        Bs[0][k0+0][r0]=b0.x; Bs[0][k0+1][r0]=b0.y; Bs[0][k0+2][r0]=b0.z; Bs[0][k0+3][r0]=b0.w;
        Bs[0][k1+0][r1]=b1.x; Bs[0][k1+1][r1]=b1.y; Bs[0][k1+2][r1]=b1.z; Bs[0][k1+3][r1]=b1.w;
    }
    __syncthreads();

    unsigned long long acc[8][8];
    #pragma unroll
    for (int ii = 0; ii < 8; ii++)
        #pragma unroll
        for (int jp = 0; jp < 8; jp++) acc[ii][jp] = 0ull;

    for (int kt = 0; kt < NCHUNK; kt++) {
        int cur = kt & 1;

        float4 a0, a1, b0, b1;
        if (kt + 1 < NCHUNK) {
            int kof = (kt + 1) * KC;
            a0 = *(const float4*)(Ab + (size_t)r0 * PDn + kof + c0 * 4);
            a1 = *(const float4*)(Ab + (size_t)r1 * PDn + kof + c1 * 4);
            b0 = *(const float4*)(Bb + (size_t)r0 * PDn + kof + c0 * 4);
            b1 = *(const float4*)(Bb + (size_t)r1 * PDn + kof + c1 * 4);
        }

        #pragma unroll
        for (int k = 0; k < KC; k++) {
            float4 av0 = *(const float4*)&As[cur][k][tm];
            float4 av1 = *(const float4*)&As[cur][k][tm + 4];
            unsigned long long A[8];
            A[0] = bcast2(av0.x); A[1] = bcast2(av0.y);
            A[2] = bcast2(av0.z); A[3] = bcast2(av0.w);
            A[4] = bcast2(av1.x); A[5] = bcast2(av1.y);
            A[6] = bcast2(av1.z); A[7] = bcast2(av1.w);

            unsigned long long Bv[8];
            ulonglong2 q0 = *(const ulonglong2*)&Bs[cur][k][tn + 0];
            ulonglong2 q1 = *(const ulonglong2*)&Bs[cur][k][tn + 4];
            ulonglong2 q2 = *(const ulonglong2*)&Bs[cur][k][tn + 8];
            ulonglong2 q3 = *(const ulonglong2*)&Bs[cur][k][tn + 12];
            Bv[0]=q0.x; Bv[1]=q0.y; Bv[2]=q1.x; Bv[3]=q1.y;
            Bv[4]=q2.x; Bv[5]=q2.y; Bv[6]=q3.x; Bv[7]=q3.y;

            #pragma unroll
            for (int ii = 0; ii < 8; ii++)
                #pragma unroll
                for (int jp = 0; jp < 8; jp++)
                    fma2(acc[ii][jp], A[ii], Bv[jp]);
        }

        if (kt + 1 < NCHUNK) {
            int nxt = cur ^ 1;
            int k0 = c0 * 4, k1 = c1 * 4;
            As[nxt][k0+0][r0]=a0.x; As[nxt][k0+1][r0]=a0.y; As[nxt][k0+2][r0]=a0.z; As[nxt][k0+3][r0]=a0.w;
            As[nxt][k1+0][r1]=a1.x; As[nxt][k1+1][r1]=a1.y; As[nxt][k1+2][r1]=a1.z; As[nxt][k1+3][r1]=a1.w;
            Bs[nxt][k0+0][r0]=b0.x; Bs[nxt][k0+1][r0]=b0.y; Bs[nxt][k0+2][r0]=b0.z; Bs[nxt][k0+3][r0]=b0.w;
            Bs[nxt][k1+0][r1]=b1.x; Bs[nxt][k1+1][r1]=b1.y; Bs[nxt][k1+2][r1]=b1.z; Bs[nxt][k1+3][r1]=b1.w;
        }
        __syncthreads();
    }

    // epilogue: dpair = sqrt(max(sq_i + sq_j - 2*inner, eps))
    #pragma unroll
    for (int ii = 0; ii < 8; ii++) {
        float sqa = sqi[tm + ii];
        size_t rbase = ((size_t)p << 20) + ((size_t)(ti + tm + ii) << 10) + tj + tn;
        #pragma unroll
        for (int jp = 0; jp < 8; jp++) {
            float2 in = unpack2(acc[ii][jp]);
            float2 v;
            v.x = sqrtf(fmaxf(sqa + sqj[tn + 2*jp]     - 2.0f * in.x, EPSV));
            v.y = sqrtf(fmaxf(sqa + sqj[tn + 2*jp + 1] - 2.0f * in.y, EPSV));
            *(float2*)&g_dpair[rbase + 2*jp] = v;
        }
    }
}

// ---------------- K4: masked margin reduction ------------------------------
__global__ void epilogue_kernel() {
    int tid = threadIdx.x;
    float accv = 0.f, accm = 0.f;
    int base = blockIdx.x * 4096;
    for (int t = 0; t < 16; t++) {
        int idx = base + t * 256 + tid;
        int i = idx >> 10, j = idx & 1023;
        if (g_lab[i] != g_lab[j]) {
            float daa = 0.f;
            #pragma unroll
            for (int p = 0; p < Pn; p++)
                daa += g_dpair[((size_t)p << 20) + idx];
            float v = g_dap[i] + g_dap[j] - daa + MARGIN;
            accv += fmaxf(v, 0.f);
            accm += 1.f;
        }
    }
    __shared__ float sv[256], sm[256];
    sv[tid] = accv; sm[tid] = accm;
    __syncthreads();
    for (int o = 128; o > 0; o >>= 1) {
        if (tid < o) { sv[tid] += sv[tid + o]; sm[tid] += sm[tid + o]; }
        __syncthreads();
    }
    if (tid == 0) {
        g_part[blockIdx.x * 2 + 0] = sv[0];
        g_part[blockIdx.x * 2 + 1] = sm[0];
    }
}

__global__ void finalize_kernel(float* __restrict__ out) {
    int tid = threadIdx.x;
    __shared__ float sv[256], sm[256];
    sv[tid] = g_part[tid * 2 + 0];
    sm[tid] = g_part[tid * 2 + 1];
    __syncthreads();
    for (int o = 128; o > 0; o >>= 1) {
        if (tid < o) { sv[tid] += sv[tid + o]; sm[tid] += sm[tid + o]; }
        __syncthreads();
    }
    if (tid == 0) out[0] = sv[0] / sm[0];
}

// ---------------- launch ----------------------------------------------------
extern "C" void kernel_launch(void* const* d_in, const int* in_sizes, int n_in,
                              void* d_out, int out_size) {
    const float* f    = (const float*)d_in[0];
    const int*   labr = (const int*)d_in[1];
    float*       out  = (float*)d_out;

    build_kernel<<<1, 256>>>(labr);
    centers_kernel<<<dim3(PDn / 256, NUM_IDS), 256>>>(f);
    dap_kernel<<<dim3(Bn, Pn), 256>>>(f);
    dapsum_kernel<<<4, 256>>>();
    gemm_f32x2_kernel<<<dim3(8, 8, 8), 128>>>(f);
    epilogue_kernel<<<256, 256>>>();
    finalize_kernel<<<1, 256>>>(out);
}

// round 5
// speedup vs baseline: 5.4425x; 2.6376x over previous
#include <cuda_runtime.h>
#include <cuda_bf16.h>
#include <math.h>
#include <stdint.h>

#define Bn 1024
#define Pn 8
#define Dn 2048
#define PDn (Pn * Dn)      // 16384
#define NUM_IDS 64
#define MARGIN 0.3f
#define EPSV 1e-12f

// ---------------- device scratch (static; no allocations) ----------------
__device__ int   g_lab[Bn];
__device__ int   g_idx[NUM_IDS * Bn];
__device__ int   g_cnt[NUM_IDS];
__device__ float g_centers[NUM_IDS * PDn];         // 4 MB
__device__ float g_sq[Bn * Pn];
__device__ float g_dpp[Bn * Pn];
__device__ float g_dap[Bn];
__device__ float g_dpair[(size_t)Pn * Bn * Bn];    // 32 MB (upper blocks used)
__device__ float g_part[256 * 2];

// upper-triangle tile pair map (36 pairs of 8x8 tiles)
__constant__ int c_TA[36] = {0,0,0,0,0,0,0,0, 1,1,1,1,1,1,1, 2,2,2,2,2,2,
                             3,3,3,3,3, 4,4,4,4, 5,5,5, 6,6, 7};
__constant__ int c_TB[36] = {0,1,2,3,4,5,6,7, 1,2,3,4,5,6,7, 2,3,4,5,6,7,
                             3,4,5,6,7, 4,5,6,7, 5,6,7, 6,7, 7};

// ---------------- K0: labels + per-id lists --------------------------------
__global__ void build_kernel(const int* __restrict__ raw) {
    __shared__ int is64;
    int t = threadIdx.x;
    if (t == 0) is64 = 1;
    __syncthreads();
    for (int k = t; k < 512; k += 256)
        if (raw[2 * k + 1] != 0) is64 = 0;
    __syncthreads();
    int w64 = is64;
    for (int b = t; b < Bn; b += 256) g_lab[b] = w64 ? raw[2 * b] : raw[b];
    __syncthreads();
    if (t < NUM_IDS) {
        int c = 0;
        for (int b = 0; b < Bn; b++)
            if (g_lab[b] == t) g_idx[t * Bn + (c++)] = b;
        g_cnt[t] = c;
    }
}

// ---------------- K1: class centers (float4) -------------------------------
__global__ void centers_kernel(const float* __restrict__ f) {
    int id   = blockIdx.y;
    int dim4 = blockIdx.x * 256 + threadIdx.x;   // 0..4095 (float4 index)
    int cnt = g_cnt[id];
    float4 acc = make_float4(0.f, 0.f, 0.f, 0.f);
    const int* lst = g_idx + id * Bn;
    for (int s = 0; s < cnt; s++) {
        float4 v = *(const float4*)(f + (size_t)lst[s] * PDn + dim4 * 4);
        acc.x += v.x; acc.y += v.y; acc.z += v.z; acc.w += v.w;
    }
    float inv = 1.0f / fmaxf((float)cnt, 1.0f);
    acc.x *= inv; acc.y *= inv; acc.z *= inv; acc.w *= inv;
    *(float4*)(g_centers + (size_t)id * PDn + dim4 * 4) = acc;
}

// ---------------- K2: per-(i,p) dist-to-center + squared norm (float4) ----
__global__ void dap_kernel(const float* __restrict__ f) {
    int i = blockIdx.x, p = blockIdx.y, tid = threadIdx.x;
    const float* fr = f + (size_t)i * PDn + (size_t)p * Dn + tid * 8;
    const float* cr = g_centers + (size_t)g_lab[i] * PDn + (size_t)p * Dn + tid * 8;
    float4 v0 = *(const float4*)fr;
    float4 v1 = *(const float4*)(fr + 4);
    float4 c0 = *(const float4*)cr;
    float4 c1 = *(const float4*)(cr + 4);
    float d = 0.f, s = 0.f, e;
    e = v0.x - c0.x; d += e * e; s += v0.x * v0.x;
    e = v0.y - c0.y; d += e * e; s += v0.y * v0.y;
    e = v0.z - c0.z; d += e * e; s += v0.z * v0.z;
    e = v0.w - c0.w; d += e * e; s += v0.w * v0.w;
    e = v1.x - c1.x; d += e * e; s += v1.x * v1.x;
    e = v1.y - c1.y; d += e * e; s += v1.y * v1.y;
    e = v1.z - c1.z; d += e * e; s += v1.z * v1.z;
    e = v1.w - c1.w; d += e * e; s += v1.w * v1.w;

    __shared__ float sd[256], ss[256];
    sd[tid] = d; ss[tid] = s;
    __syncthreads();
    for (int o = 128; o > 0; o >>= 1) {
        if (tid < o) { sd[tid] += sd[tid + o]; ss[tid] += ss[tid + o]; }
        __syncthreads();
    }
    if (tid == 0) {
        g_dpp[i * Pn + p] = sqrtf(fmaxf(sd[0], EPSV));
        g_sq[i * Pn + p]  = ss[0];
    }
}

__global__ void dapsum_kernel() {
    int i = blockIdx.x * 256 + threadIdx.x;
    if (i < Bn) {
        float s = 0.f;
        #pragma unroll
        for (int p = 0; p < Pn; p++) s += g_dpp[i * Pn + p];
        g_dap[i] = s;
    }
}

// ---------------- K3: fp32 SIMT GEMM, upper-triangle tiles only ------------
// CTA: blockIdx.x = tile pair (ti<=tj), blockIdx.y = p. 128x128 tile,
// 256 threads, 8x8 per thread, K-chunks of 16, double-buffer staging.
__global__ void __launch_bounds__(256) gemm_kernel(const float* __restrict__ f) {
    int pid = blockIdx.x;
    int p   = blockIdx.y;
    int ti  = c_TA[pid] * 128;
    int tj  = c_TB[pid] * 128;

    __shared__ float As[16][132];
    __shared__ float Bs[16][132];

    int tid = threadIdx.x;
    int tm = (tid >> 4) << 3;
    int tn = (tid & 15) << 3;

    const float* Ab = f + (size_t)ti * PDn + (size_t)p * Dn;
    const float* Bb = f + (size_t)tj * PDn + (size_t)p * Dn;

    float acc[8][8];
    #pragma unroll
    for (int a = 0; a < 8; a++)
        #pragma unroll
        for (int b = 0; b < 8; b++) acc[a][b] = 0.f;

    for (int kt = 0; kt < Dn; kt += 16) {
        #pragma unroll
        for (int l = 0; l < 2; l++) {
            int idx = tid + (l << 8);
            int row = idx >> 2;
            int c4  = idx & 3;
            float4 av = *(const float4*)(Ab + (size_t)row * PDn + kt + (c4 << 2));
            float4 bv = *(const float4*)(Bb + (size_t)row * PDn + kt + (c4 << 2));
            int kk = c4 << 2;
            As[kk + 0][row] = av.x; As[kk + 1][row] = av.y;
            As[kk + 2][row] = av.z; As[kk + 3][row] = av.w;
            Bs[kk + 0][row] = bv.x; Bs[kk + 1][row] = bv.y;
            Bs[kk + 2][row] = bv.z; Bs[kk + 3][row] = bv.w;
        }
        __syncthreads();
        #pragma unroll
        for (int k = 0; k < 16; k++) {
            float4 a0 = *(const float4*)&As[k][tm];
            float4 a1 = *(const float4*)&As[k][tm + 4];
            float4 b0 = *(const float4*)&Bs[k][tn];
            float4 b1 = *(const float4*)&Bs[k][tn + 4];
            float ar[8] = {a0.x, a0.y, a0.z, a0.w, a1.x, a1.y, a1.z, a1.w};
            float br[8] = {b0.x, b0.y, b0.z, b0.w, b1.x, b1.y, b1.z, b1.w};
            #pragma unroll
            for (int ii = 0; ii < 8; ii++)
                #pragma unroll
                for (int jj = 0; jj < 8; jj++)
                    acc[ii][jj] += ar[ii] * br[jj];
        }
        __syncthreads();
    }

    float sqa[8], sqb[8];
    #pragma unroll
    for (int ii = 0; ii < 8; ii++) sqa[ii] = g_sq[(ti + tm + ii) * Pn + p];
    #pragma unroll
    for (int jj = 0; jj < 8; jj++) sqb[jj] = g_sq[(tj + tn + jj) * Pn + p];

    size_t pbase = (size_t)p << 20;
    #pragma unroll
    for (int ii = 0; ii < 8; ii++) {
        size_t rbase = pbase + ((size_t)(ti + tm + ii) << 10) + (tj + tn);
        #pragma unroll
        for (int jj = 0; jj < 8; jj++) {
            float d2 = sqa[ii] + sqb[jj] - 2.0f * acc[ii][jj];
            g_dpair[rbase + jj] = sqrtf(fmaxf(d2, EPSV));
        }
    }
}

// ---------------- K4: masked margin reduction (upper triangle only) --------
__global__ void epilogue_kernel() {
    int tid = threadIdx.x;
    float accv = 0.f, accm = 0.f;
    int base = blockIdx.x * 4096;
    for (int t = 0; t < 16; t++) {
        int idx = base + t * 256 + tid;
        int i = idx >> 10, j = idx & 1023;
        if (j > i && g_lab[i] != g_lab[j]) {
            float daa = 0.f;
            #pragma unroll
            for (int p = 0; p < Pn; p++)
                daa += g_dpair[((size_t)p << 20) + idx];
            float v = g_dap[i] + g_dap[j] - daa + MARGIN;
            accv += fmaxf(v, 0.f);
            accm += 1.f;
        }
    }
    __shared__ float sv[256], sm[256];
    sv[tid] = accv; sm[tid] = accm;
    __syncthreads();
    for (int o = 128; o > 0; o >>= 1) {
        if (tid < o) { sv[tid] += sv[tid + o]; sm[tid] += sm[tid + o]; }
        __syncthreads();
    }
    if (tid == 0) {
        g_part[blockIdx.x * 2 + 0] = sv[0];
        g_part[blockIdx.x * 2 + 1] = sm[0];
    }
}

__global__ void finalize_kernel(float* __restrict__ out) {
    int tid = threadIdx.x;
    __shared__ float sv[256], sm[256];
    sv[tid] = g_part[tid * 2 + 0];
    sm[tid] = g_part[tid * 2 + 1];
    __syncthreads();
    for (int o = 128; o > 0; o >>= 1) {
        if (tid < o) { sv[tid] += sv[tid + o]; sm[tid] += sm[tid + o]; }
        __syncthreads();
    }
    if (tid == 0) out[0] = sv[0] / sm[0];
}

// ---------------- launch ----------------------------------------------------
extern "C" void kernel_launch(void* const* d_in, const int* in_sizes, int n_in,
                              void* d_out, int out_size) {
    const float* f    = (const float*)d_in[0];
    const int*   labr = (const int*)d_in[1];
    float*       out  = (float*)d_out;

    build_kernel<<<1, 256>>>(labr);
    centers_kernel<<<dim3(PDn / 1024, NUM_IDS), 256>>>(f);
    dap_kernel<<<dim3(Bn, Pn), 256>>>(f);
    dapsum_kernel<<<4, 256>>>();
    gemm_kernel<<<dim3(36, 8), 256>>>(f);
    epilogue_kernel<<<256, 256>>>();
    finalize_kernel<<<1, 256>>>(out);
}

// round 6
// speedup vs baseline: 5.7798x; 1.0620x over previous
#include <cuda_runtime.h>
#include <cuda_bf16.h>
#include <math.h>
#include <stdint.h>

#define Bn 1024
#define Pn 8
#define Dn 2048
#define PDn (Pn * Dn)      // 16384
#define NUM_IDS 64
#define MARGIN 0.3f
#define EPSV 1e-12f

// ---------------- device scratch (static; no allocations) ----------------
__device__ int   g_lab[Bn];
__device__ int   g_idx[NUM_IDS * Bn];
__device__ int   g_cnt[NUM_IDS];
__device__ float g_centers[NUM_IDS * PDn];         // 4 MB
__device__ float g_sq[Bn * Pn];
__device__ float g_dpp[Bn * Pn];
__device__ float g_dap[Bn];
__device__ float g_dpair[(size_t)Pn * Bn * Bn];    // 32 MB (upper blocks used)
__device__ float g_part[256 * 2];

// upper-triangle tile pair map (36 pairs of 8x8 tiles)
__constant__ int c_TA[36] = {0,0,0,0,0,0,0,0, 1,1,1,1,1,1,1, 2,2,2,2,2,2,
                             3,3,3,3,3, 4,4,4,4, 5,5,5, 6,6, 7};
__constant__ int c_TB[36] = {0,1,2,3,4,5,6,7, 1,2,3,4,5,6,7, 2,3,4,5,6,7,
                             3,4,5,6,7, 4,5,6,7, 5,6,7, 6,7, 7};

// ======================= f32x2 helpers =======================
__device__ __forceinline__ unsigned long long bcast2(float x) {
    unsigned long long r;
    asm("mov.b64 %0, {%1, %1};" : "=l"(r) : "f"(x));
    return r;
}
__device__ __forceinline__ void fma2(unsigned long long& d,
                                     unsigned long long a,
                                     unsigned long long b) {
    asm("fma.rn.f32x2 %0, %1, %2, %0;" : "+l"(d) : "l"(a), "l"(b));
}
__device__ __forceinline__ float2 unpack2(unsigned long long v) {
    float2 f;
    asm("mov.b64 {%0, %1}, %2;" : "=f"(f.x), "=f"(f.y) : "l"(v));
    return f;
}

// ---------------- K0: labels + per-id lists --------------------------------
__global__ void build_kernel(const int* __restrict__ raw) {
    __shared__ int is64;
    int t = threadIdx.x;
    if (t == 0) is64 = 1;
    __syncthreads();
    for (int k = t; k < 512; k += 256)
        if (raw[2 * k + 1] != 0) is64 = 0;
    __syncthreads();
    int w64 = is64;
    for (int b = t; b < Bn; b += 256) g_lab[b] = w64 ? raw[2 * b] : raw[b];
    __syncthreads();
    if (t < NUM_IDS) {
        int c = 0;
        for (int b = 0; b < Bn; b++)
            if (g_lab[b] == t) g_idx[t * Bn + (c++)] = b;
        g_cnt[t] = c;
    }
}

// ---------------- K1: class centers (float4) -------------------------------
__global__ void centers_kernel(const float* __restrict__ f) {
    int id   = blockIdx.y;
    int dim4 = blockIdx.x * 256 + threadIdx.x;   // float4 index
    int cnt = g_cnt[id];
    float4 acc = make_float4(0.f, 0.f, 0.f, 0.f);
    const int* lst = g_idx + id * Bn;
    for (int s = 0; s < cnt; s++) {
        float4 v = *(const float4*)(f + (size_t)lst[s] * PDn + dim4 * 4);
        acc.x += v.x; acc.y += v.y; acc.z += v.z; acc.w += v.w;
    }
    float inv = 1.0f / fmaxf((float)cnt, 1.0f);
    acc.x *= inv; acc.y *= inv; acc.z *= inv; acc.w *= inv;
    *(float4*)(g_centers + (size_t)id * PDn + dim4 * 4) = acc;
}

// ---------------- K2: per-(i,p) dist-to-center + squared norm (float4) ----
__global__ void dap_kernel(const float* __restrict__ f) {
    int i = blockIdx.x, p = blockIdx.y, tid = threadIdx.x;
    const float* fr = f + (size_t)i * PDn + (size_t)p * Dn + tid * 8;
    const float* cr = g_centers + (size_t)g_lab[i] * PDn + (size_t)p * Dn + tid * 8;
    float4 v0 = *(const float4*)fr;
    float4 v1 = *(const float4*)(fr + 4);
    float4 c0 = *(const float4*)cr;
    float4 c1 = *(const float4*)(cr + 4);
    float d = 0.f, s = 0.f, e;
    e = v0.x - c0.x; d += e * e; s += v0.x * v0.x;
    e = v0.y - c0.y; d += e * e; s += v0.y * v0.y;
    e = v0.z - c0.z; d += e * e; s += v0.z * v0.z;
    e = v0.w - c0.w; d += e * e; s += v0.w * v0.w;
    e = v1.x - c1.x; d += e * e; s += v1.x * v1.x;
    e = v1.y - c1.y; d += e * e; s += v1.y * v1.y;
    e = v1.z - c1.z; d += e * e; s += v1.z * v1.z;
    e = v1.w - c1.w; d += e * e; s += v1.w * v1.w;

    __shared__ float sd[256], ss[256];
    sd[tid] = d; ss[tid] = s;
    __syncthreads();
    for (int o = 128; o > 0; o >>= 1) {
        if (tid < o) { sd[tid] += sd[tid + o]; ss[tid] += ss[tid + o]; }
        __syncthreads();
    }
    if (tid == 0) {
        g_dpp[i * Pn + p] = sqrtf(fmaxf(sd[0], EPSV));
        g_sq[i * Pn + p]  = ss[0];
    }
}

__global__ void dapsum_kernel() {
    int i = blockIdx.x * 256 + threadIdx.x;
    if (i < Bn) {
        float s = 0.f;
        #pragma unroll
        for (int p = 0; p < Pn; p++) s += g_dpp[i * Pn + p];
        g_dap[i] = s;
    }
}

// ---------------- K3: fp32 GEMM via fma.rn.f32x2, upper-triangle tiles -----
// CTA: blockIdx.x = tile pair (ti<=tj), blockIdx.y = p. 128x128 tile,
// 256 threads (16x16). Thread: rows tm..tm+7 (scalar), cols 2tx+32m (pairs).
// B loaded as native float2 pairs (conflict-free); A broadcast via mov.b64.
__global__ void __launch_bounds__(256) gemm_kernel(const float* __restrict__ f) {
    int pid = blockIdx.x;
    int p   = blockIdx.y;
    int ti  = c_TA[pid] * 128;
    int tj  = c_TB[pid] * 128;

    __shared__ float As[16][132];
    __shared__ float Bs[16][132];

    int tid = threadIdx.x;
    int ty = tid >> 4, tx = tid & 15;
    int tm = ty * 8;            // 8 scalar rows
    int tc = tx * 2;            // col pairs at tc + 32*m, m=0..3

    const float* Ab = f + (size_t)ti * PDn + (size_t)p * Dn;
    const float* Bb = f + (size_t)tj * PDn + (size_t)p * Dn;

    unsigned long long acc[8][4];
    #pragma unroll
    for (int ii = 0; ii < 8; ii++)
        #pragma unroll
        for (int m = 0; m < 4; m++) acc[ii][m] = 0ull;

    for (int kt = 0; kt < Dn; kt += 16) {
        #pragma unroll
        for (int l = 0; l < 2; l++) {
            int idx = tid + (l << 8);
            int row = idx >> 2;
            int c4  = idx & 3;
            float4 av = *(const float4*)(Ab + (size_t)row * PDn + kt + (c4 << 2));
            float4 bv = *(const float4*)(Bb + (size_t)row * PDn + kt + (c4 << 2));
            int kk = c4 << 2;
            As[kk + 0][row] = av.x; As[kk + 1][row] = av.y;
            As[kk + 2][row] = av.z; As[kk + 3][row] = av.w;
            Bs[kk + 0][row] = bv.x; Bs[kk + 1][row] = bv.y;
            Bs[kk + 2][row] = bv.z; Bs[kk + 3][row] = bv.w;
        }
        __syncthreads();
        #pragma unroll
        for (int k = 0; k < 16; k++) {
            float4 a0 = *(const float4*)&As[k][tm];
            float4 a1 = *(const float4*)&As[k][tm + 4];
            unsigned long long A2[8];
            A2[0] = bcast2(a0.x); A2[1] = bcast2(a0.y);
            A2[2] = bcast2(a0.z); A2[3] = bcast2(a0.w);
            A2[4] = bcast2(a1.x); A2[5] = bcast2(a1.y);
            A2[6] = bcast2(a1.z); A2[7] = bcast2(a1.w);

            unsigned long long B2[4];
            B2[0] = *(const unsigned long long*)&Bs[k][tc];
            B2[1] = *(const unsigned long long*)&Bs[k][tc + 32];
            B2[2] = *(const unsigned long long*)&Bs[k][tc + 64];
            B2[3] = *(const unsigned long long*)&Bs[k][tc + 96];

            #pragma unroll
            for (int ii = 0; ii < 8; ii++)
                #pragma unroll
                for (int m = 0; m < 4; m++)
                    fma2(acc[ii][m], A2[ii], B2[m]);
        }
        __syncthreads();
    }

    float sqa[8], sqbx[4], sqby[4];
    #pragma unroll
    for (int ii = 0; ii < 8; ii++) sqa[ii] = g_sq[(ti + tm + ii) * Pn + p];
    #pragma unroll
    for (int m = 0; m < 4; m++) {
        sqbx[m] = g_sq[(tj + tc + 32 * m) * Pn + p];
        sqby[m] = g_sq[(tj + tc + 32 * m + 1) * Pn + p];
    }

    size_t pbase = (size_t)p << 20;
    #pragma unroll
    for (int ii = 0; ii < 8; ii++) {
        size_t rbase = pbase + ((size_t)(ti + tm + ii) << 10) + tj + tc;
        #pragma unroll
        for (int m = 0; m < 4; m++) {
            float2 in = unpack2(acc[ii][m]);
            float2 v;
            v.x = sqrtf(fmaxf(sqa[ii] + sqbx[m] - 2.0f * in.x, EPSV));
            v.y = sqrtf(fmaxf(sqa[ii] + sqby[m] - 2.0f * in.y, EPSV));
            *(float2*)&g_dpair[rbase + 32 * m] = v;
        }
    }
}

// ---------------- K4: masked margin reduction (upper triangle only) --------
__global__ void epilogue_kernel() {
    int tid = threadIdx.x;
    float accv = 0.f, accm = 0.f;
    int base = blockIdx.x * 4096;
    for (int t = 0; t < 16; t++) {
        int idx = base + t * 256 + tid;
        int i = idx >> 10, j = idx & 1023;
        if (j > i && g_lab[i] != g_lab[j]) {
            float daa = 0.f;
            #pragma unroll
            for (int p = 0; p < Pn; p++)
                daa += g_dpair[((size_t)p << 20) + idx];
            float v = g_dap[i] + g_dap[j] - daa + MARGIN;
            accv += fmaxf(v, 0.f);
            accm += 1.f;
        }
    }
    __shared__ float sv[256], sm[256];
    sv[tid] = accv; sm[tid] = accm;
    __syncthreads();
    for (int o = 128; o > 0; o >>= 1) {
        if (tid < o) { sv[tid] += sv[tid + o]; sm[tid] += sm[tid + o]; }
        __syncthreads();
    }
    if (tid == 0) {
        g_part[blockIdx.x * 2 + 0] = sv[0];
        g_part[blockIdx.x * 2 + 1] = sm[0];
    }
}

__global__ void finalize_kernel(float* __restrict__ out) {
    int tid = threadIdx.x;
    __shared__ float sv[256], sm[256];
    sv[tid] = g_part[tid * 2 + 0];
    sm[tid] = g_part[tid * 2 + 1];
    __syncthreads();
    for (int o = 128; o > 0; o >>= 1) {
        if (tid < o) { sv[tid] += sv[tid + o]; sm[tid] += sm[tid + o]; }
        __syncthreads();
    }
    if (tid == 0) out[0] = sv[0] / sm[0];
}

// ---------------- launch ----------------------------------------------------
extern "C" void kernel_launch(void* const* d_in, const int* in_sizes, int n_in,
                              void* d_out, int out_size) {
    const float* f    = (const float*)d_in[0];
    const int*   labr = (const int*)d_in[1];
    float*       out  = (float*)d_out;

    build_kernel<<<1, 256>>>(labr);
    centers_kernel<<<dim3(PDn / 1024, NUM_IDS), 256>>>(f);
    dap_kernel<<<dim3(Bn, Pn), 256>>>(f);
    dapsum_kernel<<<4, 256>>>();
    gemm_kernel<<<dim3(36, 8), 256>>>(f);
    epilogue_kernel<<<256, 256>>>();
    finalize_kernel<<<1, 256>>>(out);
}

// round 7
// speedup vs baseline: 5.7878x; 1.0014x over previous
#include <cuda_runtime.h>
#include <cuda_fp16.h>
#include <math.h>
#include <stdint.h>

#define Bn 1024
#define Pn 8
#define Dn 2048
#define PDn (Pn * Dn)      // 16384
#define NUM_IDS 64
#define MARGIN 0.3f
#define EPSV 1e-12f

// ---------------- device scratch (static; no allocations) ----------------
__device__ int    g_lab[Bn];
__device__ int    g_idx[NUM_IDS * Bn];
__device__ int    g_cnt[NUM_IDS];
__device__ float  g_centers[NUM_IDS * PDn];        // 4 MB
__device__ float  g_sq[Bn * Pn];
__device__ float  g_dpp[Bn * Pn];
__device__ float  g_dap[Bn];
__device__ float  g_dpair[(size_t)Pn * Bn * Bn];   // 32 MB (upper blocks used)
__device__ float  g_part[256 * 2];
__device__ __half g_fh16[(size_t)Bn * PDn];        // 32 MB fp16 copy of f

// upper-triangle tile pair map (36 pairs of 8x8 tiles)
__constant__ int c_TA[36] = {0,0,0,0,0,0,0,0, 1,1,1,1,1,1,1, 2,2,2,2,2,2,
                             3,3,3,3,3, 4,4,4,4, 5,5,5, 6,6, 7};
__constant__ int c_TB[36] = {0,1,2,3,4,5,6,7, 1,2,3,4,5,6,7, 2,3,4,5,6,7,
                             3,4,5,6,7, 4,5,6,7, 5,6,7, 6,7, 7};

// ---------------- K-1: fp32 -> fp16 convert --------------------------------
__global__ void conv_kernel(const float* __restrict__ f) {
    size_t i = ((size_t)blockIdx.x * 256 + threadIdx.x) * 8;
    float4 a = *(const float4*)(f + i);
    float4 b = *(const float4*)(f + i + 4);
    __half2 h0 = __floats2half2_rn(a.x, a.y);
    __half2 h1 = __floats2half2_rn(a.z, a.w);
    __half2 h2 = __floats2half2_rn(b.x, b.y);
    __half2 h3 = __floats2half2_rn(b.z, b.w);
    uint4 o;
    o.x = *(uint32_t*)&h0; o.y = *(uint32_t*)&h1;
    o.z = *(uint32_t*)&h2; o.w = *(uint32_t*)&h3;
    *(uint4*)(g_fh16 + i) = o;
}

// ---------------- K0: labels + per-id lists --------------------------------
__global__ void build_kernel(const int* __restrict__ raw) {
    __shared__ int is64;
    int t = threadIdx.x;
    if (t == 0) is64 = 1;
    __syncthreads();
    for (int k = t; k < 512; k += 256)
        if (raw[2 * k + 1] != 0) is64 = 0;
    __syncthreads();
    int w64 = is64;
    for (int b = t; b < Bn; b += 256) g_lab[b] = w64 ? raw[2 * b] : raw[b];
    __syncthreads();
    if (t < NUM_IDS) {
        int c = 0;
        for (int b = 0; b < Bn; b++)
            if (g_lab[b] == t) g_idx[t * Bn + (c++)] = b;
        g_cnt[t] = c;
    }
}

// ---------------- K1: class centers (float4) -------------------------------
__global__ void centers_kernel(const float* __restrict__ f) {
    int id   = blockIdx.y;
    int dim4 = blockIdx.x * 256 + threadIdx.x;
    int cnt = g_cnt[id];
    float4 acc = make_float4(0.f, 0.f, 0.f, 0.f);
    const int* lst = g_idx + id * Bn;
    for (int s = 0; s < cnt; s++) {
        float4 v = *(const float4*)(f + (size_t)lst[s] * PDn + dim4 * 4);
        acc.x += v.x; acc.y += v.y; acc.z += v.z; acc.w += v.w;
    }
    float inv = 1.0f / fmaxf((float)cnt, 1.0f);
    acc.x *= inv; acc.y *= inv; acc.z *= inv; acc.w *= inv;
    *(float4*)(g_centers + (size_t)id * PDn + dim4 * 4) = acc;
}

// ---------------- K2: per-(i,p) dist-to-center + squared norm (float4) ----
__global__ void dap_kernel(const float* __restrict__ f) {
    int i = blockIdx.x, p = blockIdx.y, tid = threadIdx.x;
    const float* fr = f + (size_t)i * PDn + (size_t)p * Dn + tid * 8;
    const float* cr = g_centers + (size_t)g_lab[i] * PDn + (size_t)p * Dn + tid * 8;
    float4 v0 = *(const float4*)fr;
    float4 v1 = *(const float4*)(fr + 4);
    float4 c0 = *(const float4*)cr;
    float4 c1 = *(const float4*)(cr + 4);
    float d = 0.f, s = 0.f, e;
    e = v0.x - c0.x; d += e * e; s += v0.x * v0.x;
    e = v0.y - c0.y; d += e * e; s += v0.y * v0.y;
    e = v0.z - c0.z; d += e * e; s += v0.z * v0.z;
    e = v0.w - c0.w; d += e * e; s += v0.w * v0.w;
    e = v1.x - c1.x; d += e * e; s += v1.x * v1.x;
    e = v1.y - c1.y; d += e * e; s += v1.y * v1.y;
    e = v1.z - c1.z; d += e * e; s += v1.z * v1.z;
    e = v1.w - c1.w; d += e * e; s += v1.w * v1.w;

    __shared__ float sd[256], ss[256];
    sd[tid] = d; ss[tid] = s;
    __syncthreads();
    for (int o = 128; o > 0; o >>= 1) {
        if (tid < o) { sd[tid] += sd[tid + o]; ss[tid] += ss[tid + o]; }
        __syncthreads();
    }
    if (tid == 0) {
        g_dpp[i * Pn + p] = sqrtf(fmaxf(sd[0], EPSV));
        g_sq[i * Pn + p]  = ss[0];
    }
}

__global__ void dapsum_kernel() {
    int i = blockIdx.x * 256 + threadIdx.x;
    if (i < Bn) {
        float s = 0.f;
        #pragma unroll
        for (int p = 0; p < Pn; p++) s += g_dpp[i * Pn + p];
        g_dap[i] = s;
    }
}

// ---------------- K3: fp16x2 HFMA2 GEMM, upper-triangle tiles --------------
// CTA: blockIdx.x = tile pair (ti<=tj), blockIdx.y = p. 128x128 tile,
// 512 threads (16 ty x 32 tx), thread tile 8 rows x 4 cols.
// acc2[i][j] (half2) accumulates even/odd k lanes; promoted to fp32 every
// 128 k. smem holds k-pairs: As[kp][row] = (a[row,2kp], a[row,2kp+1]).
#define KC 64
#define KP (KC / 2)          // 32 k-pairs per chunk
#define NCH (Dn / KC)        // 32 chunks

__global__ void __launch_bounds__(512) gemm_kernel() {
    __shared__ __half2 As[KP][132];
    __shared__ __half2 Bs[KP][132];

    int tid = threadIdx.x;
    int ty = tid >> 5, tx = tid & 31;
    int tm = ty * 8, tn = tx * 4;
    int pid = blockIdx.x, p = blockIdx.y;
    int ti = c_TA[pid] * 128, tj = c_TB[pid] * 128;

    const __half* Ab = g_fh16 + (size_t)ti * PDn + (size_t)p * Dn;
    const __half* Bb = g_fh16 + (size_t)tj * PDn + (size_t)p * Dn;

    // staging: 512 threads, per matrix 128 rows x 8 groups (of 8 halves)
    int srow = tid & 127;
    int sgrp0 = tid >> 7;    // 0..3; +4 on second pass

    __half2 acc2[8][4];
    float   acc[8][4];
    const __half2 hz = __floats2half2_rn(0.f, 0.f);
    #pragma unroll
    for (int i = 0; i < 8; i++)
        #pragma unroll
        for (int j = 0; j < 4; j++) { acc2[i][j] = hz; acc[i][j] = 0.f; }

    for (int ch = 0; ch < NCH; ch++) {
        int k0 = ch * KC;
        __syncthreads();
        #pragma unroll
        for (int u = 0; u < 2; u++) {
            int grp = sgrp0 + u * 4;
            uint4 av = *(const uint4*)(Ab + (size_t)srow * PDn + k0 + grp * 8);
            uint4 bv = *(const uint4*)(Bb + (size_t)srow * PDn + k0 + grp * 8);
            int kp0 = grp * 4;
            const __half2* ah = (const __half2*)&av;
            const __half2* bh = (const __half2*)&bv;
            #pragma unroll
            for (int q = 0; q < 4; q++) {
                As[kp0 + q][srow] = ah[q];
                Bs[kp0 + q][srow] = bh[q];
            }
        }
        __syncthreads();

        #pragma unroll
        for (int kp = 0; kp < KP; kp++) {
            uint4 aa0 = *(const uint4*)&As[kp][tm];
            uint4 aa1 = *(const uint4*)&As[kp][tm + 4];
            uint4 bb  = *(const uint4*)&Bs[kp][tn];
            __half2 a[8], b[4];
            a[0] = ((const __half2*)&aa0)[0]; a[1] = ((const __half2*)&aa0)[1];
            a[2] = ((const __half2*)&aa0)[2]; a[3] = ((const __half2*)&aa0)[3];
            a[4] = ((const __half2*)&aa1)[0]; a[5] = ((const __half2*)&aa1)[1];
            a[6] = ((const __half2*)&aa1)[2]; a[7] = ((const __half2*)&aa1)[3];
            b[0] = ((const __half2*)&bb)[0];  b[1] = ((const __half2*)&bb)[1];
            b[2] = ((const __half2*)&bb)[2];  b[3] = ((const __half2*)&bb)[3];
            #pragma unroll
            for (int i = 0; i < 8; i++)
                #pragma unroll
                for (int j = 0; j < 4; j++)
                    acc2[i][j] = __hfma2(a[i], b[j], acc2[i][j]);
        }

        if (ch & 1) {   // promote every 128 k
            #pragma unroll
            for (int i = 0; i < 8; i++)
                #pragma unroll
                for (int j = 0; j < 4; j++) {
                    float2 fv = __half22float2(acc2[i][j]);
                    acc[i][j] += fv.x + fv.y;
                    acc2[i][j] = hz;
                }
        }
    }

    // epilogue: dpair = sqrt(max(sq_i + sq_j - 2*inner, eps))
    float sqa[8], sqb[4];
    #pragma unroll
    for (int i = 0; i < 8; i++) sqa[i] = g_sq[(ti + tm + i) * Pn + p];
    #pragma unroll
    for (int j = 0; j < 4; j++) sqb[j] = g_sq[(tj + tn + j) * Pn + p];

    size_t pbase = (size_t)p << 20;
    #pragma unroll
    for (int i = 0; i < 8; i++) {
        float4 v;
        v.x = sqrtf(fmaxf(sqa[i] + sqb[0] - 2.0f * acc[i][0], EPSV));
        v.y = sqrtf(fmaxf(sqa[i] + sqb[1] - 2.0f * acc[i][1], EPSV));
        v.z = sqrtf(fmaxf(sqa[i] + sqb[2] - 2.0f * acc[i][2], EPSV));
        v.w = sqrtf(fmaxf(sqa[i] + sqb[3] - 2.0f * acc[i][3], EPSV));
        *(float4*)&g_dpair[pbase + ((size_t)(ti + tm + i) << 10) + tj + tn] = v;
    }
}

// ---------------- K4: masked margin reduction (upper triangle only) --------
__global__ void epilogue_kernel() {
    int tid = threadIdx.x;
    float accv = 0.f, accm = 0.f;
    int base = blockIdx.x * 4096;
    for (int t = 0; t < 16; t++) {
        int idx = base + t * 256 + tid;
        int i = idx >> 10, j = idx & 1023;
        if (j > i && g_lab[i] != g_lab[j]) {
            float daa = 0.f;
            #pragma unroll
            for (int p = 0; p < Pn; p++)
                daa += g_dpair[((size_t)p << 20) + idx];
            float v = g_dap[i] + g_dap[j] - daa + MARGIN;
            accv += fmaxf(v, 0.f);
            accm += 1.f;
        }
    }
    __shared__ float sv[256], sm[256];
    sv[tid] = accv; sm[tid] = accm;
    __syncthreads();
    for (int o = 128; o > 0; o >>= 1) {
        if (tid < o) { sv[tid] += sv[tid + o]; sm[tid] += sm[tid + o]; }
        __syncthreads();
    }
    if (tid == 0) {
        g_part[blockIdx.x * 2 + 0] = sv[0];
        g_part[blockIdx.x * 2 + 1] = sm[0];
    }
}

__global__ void finalize_kernel(float* __restrict__ out) {
    int tid = threadIdx.x;
    __shared__ float sv[256], sm[256];
    sv[tid] = g_part[tid * 2 + 0];
    sm[tid] = g_part[tid * 2 + 1];
    __syncthreads();
    for (int o = 128; o > 0; o >>= 1) {
        if (tid < o) { sv[tid] += sv[tid + o]; sm[tid] += sm[tid + o]; }
        __syncthreads();
    }
    if (tid == 0) out[0] = sv[0] / sm[0];
}

// ---------------- launch ----------------------------------------------------
extern "C" void kernel_launch(void* const* d_in, const int* in_sizes, int n_in,
                              void* d_out, int out_size) {
    const float* f    = (const float*)d_in[0];
    const int*   labr = (const int*)d_in[1];
    float*       out  = (float*)d_out;

    conv_kernel<<<(Bn * PDn) / (256 * 8), 256>>>(f);
    build_kernel<<<1, 256>>>(labr);
    centers_kernel<<<dim3(PDn / 1024, NUM_IDS), 256>>>(f);
    dap_kernel<<<dim3(Bn, Pn), 256>>>(f);
    dapsum_kernel<<<4, 256>>>();
    gemm_kernel<<<dim3(36, 8), 512>>>();
    epilogue_kernel<<<256, 256>>>();
    finalize_kernel<<<1, 256>>>(out);
}

// round 8
// speedup vs baseline: 6.5199x; 1.1265x over previous
#include <cuda_runtime.h>
#include <cuda_fp16.h>
#include <math.h>
#include <stdint.h>

#define Bn 1024
#define Pn 8
#define Dn 2048
#define PDn (Pn * Dn)      // 16384
#define NUM_IDS 64
#define MARGIN 0.3f
#define EPSV 1e-12f

// ---------------- device scratch (static; no allocations) ----------------
__device__ int    g_lab[Bn];
__device__ int    g_idx[NUM_IDS * Bn];
__device__ int    g_cnt[NUM_IDS];
__device__ float  g_centers[NUM_IDS * PDn];        // 4 MB
__device__ float  g_sq[Bn * Pn];
__device__ float  g_dpp[Bn * Pn];
__device__ float  g_dap[Bn];
__device__ float  g_dpair[(size_t)Pn * Bn * Bn];   // 32 MB (upper blocks used)
__device__ float  g_part[256 * 2];
__device__ __half g_fh16[(size_t)Bn * PDn];        // 32 MB fp16 copy of f

// upper-triangle tile pair map (36 pairs of 8x8 tiles)
__constant__ int c_TA[36] = {0,0,0,0,0,0,0,0, 1,1,1,1,1,1,1, 2,2,2,2,2,2,
                             3,3,3,3,3, 4,4,4,4, 5,5,5, 6,6, 7};
__constant__ int c_TB[36] = {0,1,2,3,4,5,6,7, 1,2,3,4,5,6,7, 2,3,4,5,6,7,
                             3,4,5,6,7, 4,5,6,7, 5,6,7, 6,7, 7};

// ---------------- K0: labels + per-id lists --------------------------------
__global__ void build_kernel(const int* __restrict__ raw) {
    __shared__ int is64;
    int t = threadIdx.x;
    if (t == 0) is64 = 1;
    __syncthreads();
    for (int k = t; k < 512; k += 256)
        if (raw[2 * k + 1] != 0) is64 = 0;
    __syncthreads();
    int w64 = is64;
    for (int b = t; b < Bn; b += 256) g_lab[b] = w64 ? raw[2 * b] : raw[b];
    __syncthreads();
    if (t < NUM_IDS) {
        int c = 0;
        for (int b = 0; b < Bn; b++)
            if (g_lab[b] == t) g_idx[t * Bn + (c++)] = b;
        g_cnt[t] = c;
    }
}

// ---------------- K1: class centers (float4) -------------------------------
__global__ void centers_kernel(const float* __restrict__ f) {
    int id   = blockIdx.y;
    int dim4 = blockIdx.x * 256 + threadIdx.x;
    int cnt = g_cnt[id];
    float4 acc = make_float4(0.f, 0.f, 0.f, 0.f);
    const int* lst = g_idx + id * Bn;
    for (int s = 0; s < cnt; s++) {
        float4 v = *(const float4*)(f + (size_t)lst[s] * PDn + dim4 * 4);
        acc.x += v.x; acc.y += v.y; acc.z += v.z; acc.w += v.w;
    }
    float inv = 1.0f / fmaxf((float)cnt, 1.0f);
    acc.x *= inv; acc.y *= inv; acc.z *= inv; acc.w *= inv;
    *(float4*)(g_centers + (size_t)id * PDn + dim4 * 4) = acc;
}

// ---------------- K2: dist-to-center + sq norm + fp16 convert (fused) -----
__global__ void dap_kernel(const float* __restrict__ f) {
    int i = blockIdx.x, p = blockIdx.y, tid = threadIdx.x;
    size_t off = (size_t)i * PDn + (size_t)p * Dn + tid * 8;
    const float* fr = f + off;
    const float* cr = g_centers + (size_t)g_lab[i] * PDn + (size_t)p * Dn + tid * 8;
    float4 v0 = *(const float4*)fr;
    float4 v1 = *(const float4*)(fr + 4);
    float4 c0 = *(const float4*)cr;
    float4 c1 = *(const float4*)(cr + 4);

    // fused fp32 -> fp16 conversion (replaces conv_kernel)
    __half2 h0 = __floats2half2_rn(v0.x, v0.y);
    __half2 h1 = __floats2half2_rn(v0.z, v0.w);
    __half2 h2 = __floats2half2_rn(v1.x, v1.y);
    __half2 h3 = __floats2half2_rn(v1.z, v1.w);
    uint4 o;
    o.x = *(uint32_t*)&h0; o.y = *(uint32_t*)&h1;
    o.z = *(uint32_t*)&h2; o.w = *(uint32_t*)&h3;
    *(uint4*)(g_fh16 + off) = o;

    float d = 0.f, s = 0.f, e;
    e = v0.x - c0.x; d += e * e; s += v0.x * v0.x;
    e = v0.y - c0.y; d += e * e; s += v0.y * v0.y;
    e = v0.z - c0.z; d += e * e; s += v0.z * v0.z;
    e = v0.w - c0.w; d += e * e; s += v0.w * v0.w;
    e = v1.x - c1.x; d += e * e; s += v1.x * v1.x;
    e = v1.y - c1.y; d += e * e; s += v1.y * v1.y;
    e = v1.z - c1.z; d += e * e; s += v1.z * v1.z;
    e = v1.w - c1.w; d += e * e; s += v1.w * v1.w;

    __shared__ float sd[256], ss[256];
    sd[tid] = d; ss[tid] = s;
    __syncthreads();
    for (int o2 = 128; o2 > 0; o2 >>= 1) {
        if (tid < o2) { sd[tid] += sd[tid + o2]; ss[tid] += ss[tid + o2]; }
        __syncthreads();
    }
    if (tid == 0) {
        g_dpp[i * Pn + p] = sqrtf(fmaxf(sd[0], EPSV));
        g_sq[i * Pn + p]  = ss[0];
    }
}

__global__ void dapsum_kernel() {
    int i = blockIdx.x * 256 + threadIdx.x;
    if (i < Bn) {
        float s = 0.f;
        #pragma unroll
        for (int p = 0; p < Pn; p++) s += g_dpp[i * Pn + p];
        g_dap[i] = s;
    }
}

// ---------------- K3: fp16x2 HFMA2 GEMM, software-pipelined ----------------
// CTA: blockIdx.x = tile pair (ti<=tj), blockIdx.y = p. 128x128 tile,
// 512 threads (16 ty x 32 tx), thread tile 8 rows x 4 cols.
// Register-prefetch pipeline: global loads for chunk c+1 issue between the
// two syncs of chunk c and complete under the 32-kp compute phase.
#define KC 64
#define KP (KC / 2)          // 32 k-pairs per chunk
#define NCH (Dn / KC)        // 32 chunks

__global__ void __launch_bounds__(512) gemm_kernel() {
    __shared__ __half2 As[KP][132];
    __shared__ __half2 Bs[KP][132];

    int tid = threadIdx.x;
    int ty = tid >> 5, tx = tid & 31;
    int tm = ty * 8, tn = tx * 4;
    int pid = blockIdx.x, p = blockIdx.y;
    int ti = c_TA[pid] * 128, tj = c_TB[pid] * 128;

    const __half* Ab = g_fh16 + (size_t)ti * PDn + (size_t)p * Dn;
    const __half* Bb = g_fh16 + (size_t)tj * PDn + (size_t)p * Dn;

    int srow = tid & 127;
    int sg0  = tid >> 7;     // 0..3; groups sg0 and sg0+4

    __half2 acc2[8][4];
    float   acc[8][4];
    const __half2 hz = __floats2half2_rn(0.f, 0.f);
    #pragma unroll
    for (int i = 0; i < 8; i++)
        #pragma unroll
        for (int j = 0; j < 4; j++) { acc2[i][j] = hz; acc[i][j] = 0.f; }

    // prefetch chunk 0
    uint4 pa[2], pb[2];
    #pragma unroll
    for (int u = 0; u < 2; u++) {
        int grp = sg0 + u * 4;
        pa[u] = *(const uint4*)(Ab + (size_t)srow * PDn + grp * 8);
        pb[u] = *(const uint4*)(Bb + (size_t)srow * PDn + grp * 8);
    }

    for (int ch = 0; ch < NCH; ch++) {
        // store prefetched chunk into smem
        #pragma unroll
        for (int u = 0; u < 2; u++) {
            int kp0 = (sg0 + u * 4) * 4;
            const __half2* ah = (const __half2*)&pa[u];
            const __half2* bh = (const __half2*)&pb[u];
            #pragma unroll
            for (int q = 0; q < 4; q++) {
                As[kp0 + q][srow] = ah[q];
                Bs[kp0 + q][srow] = bh[q];
            }
        }
        __syncthreads();

        // issue prefetch for next chunk (completes under compute)
        if (ch + 1 < NCH) {
            int k0 = (ch + 1) * KC;
            #pragma unroll
            for (int u = 0; u < 2; u++) {
                int grp = sg0 + u * 4;
                pa[u] = *(const uint4*)(Ab + (size_t)srow * PDn + k0 + grp * 8);
                pb[u] = *(const uint4*)(Bb + (size_t)srow * PDn + k0 + grp * 8);
            }
        }

        #pragma unroll
        for (int kp = 0; kp < KP; kp++) {
            uint4 aa0 = *(const uint4*)&As[kp][tm];
            uint4 aa1 = *(const uint4*)&As[kp][tm + 4];
            uint4 bb  = *(const uint4*)&Bs[kp][tn];
            __half2 a[8], b[4];
            a[0] = ((const __half2*)&aa0)[0]; a[1] = ((const __half2*)&aa0)[1];
            a[2] = ((const __half2*)&aa0)[2]; a[3] = ((const __half2*)&aa0)[3];
            a[4] = ((const __half2*)&aa1)[0]; a[5] = ((const __half2*)&aa1)[1];
            a[6] = ((const __half2*)&aa1)[2]; a[7] = ((const __half2*)&aa1)[3];
            b[0] = ((const __half2*)&bb)[0];  b[1] = ((const __half2*)&bb)[1];
            b[2] = ((const __half2*)&bb)[2];  b[3] = ((const __half2*)&bb)[3];
            #pragma unroll
            for (int i = 0; i < 8; i++)
                #pragma unroll
                for (int j = 0; j < 4; j++)
                    acc2[i][j] = __hfma2(a[i], b[j], acc2[i][j]);
        }

        if (ch & 1) {   // promote every 128 k
            #pragma unroll
            for (int i = 0; i < 8; i++)
                #pragma unroll
                for (int j = 0; j < 4; j++) {
                    float2 fv = __half22float2(acc2[i][j]);
                    acc[i][j] += fv.x + fv.y;
                    acc2[i][j] = hz;
                }
        }
        __syncthreads();
    }

    // epilogue: dpair = sqrt(max(sq_i + sq_j - 2*inner, eps))
    float sqa[8], sqb[4];
    #pragma unroll
    for (int i = 0; i < 8; i++) sqa[i] = g_sq[(ti + tm + i) * Pn + p];
    #pragma unroll
    for (int j = 0; j < 4; j++) sqb[j] = g_sq[(tj + tn + j) * Pn + p];

    size_t pbase = (size_t)p << 20;
    #pragma unroll
    for (int i = 0; i < 8; i++) {
        float4 v;
        v.x = sqrtf(fmaxf(sqa[i] + sqb[0] - 2.0f * acc[i][0], EPSV));
        v.y = sqrtf(fmaxf(sqa[i] + sqb[1] - 2.0f * acc[i][1], EPSV));
        v.z = sqrtf(fmaxf(sqa[i] + sqb[2] - 2.0f * acc[i][2], EPSV));
        v.w = sqrtf(fmaxf(sqa[i] + sqb[3] - 2.0f * acc[i][3], EPSV));
        *(float4*)&g_dpair[pbase + ((size_t)(ti + tm + i) << 10) + tj + tn] = v;
    }
}

// ---------------- K4: masked margin reduction (upper triangle only) --------
__global__ void epilogue_kernel() {
    int tid = threadIdx.x;
    float accv = 0.f, accm = 0.f;
    int base = blockIdx.x * 4096;
    for (int t = 0; t < 16; t++) {
        int idx = base + t * 256 + tid;
        int i = idx >> 10, j = idx & 1023;
        if (j > i && g_lab[i] != g_lab[j]) {
            float daa = 0.f;
            #pragma unroll
            for (int p = 0; p < Pn; p++)
                daa += g_dpair[((size_t)p << 20) + idx];
            float v = g_dap[i] + g_dap[j] - daa + MARGIN;
            accv += fmaxf(v, 0.f);
            accm += 1.f;
        }
    }
    __shared__ float sv[256], sm[256];
    sv[tid] = accv; sm[tid] = accm;
    __syncthreads();
    for (int o = 128; o > 0; o >>= 1) {
        if (tid < o) { sv[tid] += sv[tid + o]; sm[tid] += sm[tid + o]; }
        __syncthreads();
    }
    if (tid == 0) {
        g_part[blockIdx.x * 2 + 0] = sv[0];
        g_part[blockIdx.x * 2 + 1] = sm[0];
    }
}

__global__ void finalize_kernel(float* __restrict__ out) {
    int tid = threadIdx.x;
    __shared__ float sv[256], sm[256];
    sv[tid] = g_part[tid * 2 + 0];
    sm[tid] = g_part[tid * 2 + 1];
    __syncthreads();
    for (int o = 128; o > 0; o >>= 1) {
        if (tid < o) { sv[tid] += sv[tid + o]; sm[tid] += sm[tid + o]; }
        __syncthreads();
    }
    if (tid == 0) out[0] = sv[0] / sm[0];
}

// ---------------- launch ----------------------------------------------------
extern "C" void kernel_launch(void* const* d_in, const int* in_sizes, int n_in,
                              void* d_out, int out_size) {
    const float* f    = (const float*)d_in[0];
    const int*   labr = (const int*)d_in[1];
    float*       out  = (float*)d_out;

    build_kernel<<<1, 256>>>(labr);
    centers_kernel<<<dim3(PDn / 1024, NUM_IDS), 256>>>(f);
    dap_kernel<<<dim3(Bn, Pn), 256>>>(f);
    dapsum_kernel<<<4, 256>>>();
    gemm_kernel<<<dim3(36, 8), 512>>>();
    epilogue_kernel<<<256, 256>>>();
    finalize_kernel<<<1, 256>>>(out);
}